// round 6
// baseline (speedup 1.0000x reference)
#include <cuda_runtime.h>
#include <cuda_bf16.h>
#include <stdint.h>
#include <math.h>

#define NN 4096
#define HH 256
#define EE 65536
#define SPLITS 8

// ---------------- device scratch ----------------
__device__ float g_h[NN * HH];
__device__ float g_xlin[NN * HH];
__device__ float g_qkv[NN * 3 * HH];
__device__ float g_attn[NN * HH];
__device__ float g_proj[NN * HH];
__device__ float g_agg[NN * HH];
__device__ float g_out[NN * HH];
__device__ float g_ffn[NN * 2 * HH];
__device__ float g_hid[NN * HH];
__device__ float g_deg[NN];
__device__ float g_dinv[NN];
__device__ float g_opart[SPLITS * NN * HH];
__device__ float g_mpart[SPLITS * 4 * NN];
__device__ float g_lpart[SPLITS * 4 * NN];

// ---------------- helpers ----------------
__device__ __forceinline__ uint32_t f2tf(float f) {
    uint32_t u;
    asm("cvt.rna.tf32.f32 %0, %1;" : "=r"(u) : "f"(f));
    return u;
}

__device__ __forceinline__ void mma_tf32(float c[4], const uint32_t a[4], const uint32_t b[2]) {
    asm volatile(
        "mma.sync.aligned.m16n8k8.row.col.f32.tf32.tf32.f32 "
        "{%0,%1,%2,%3},{%4,%5,%6,%7},{%8,%9},{%0,%1,%2,%3};\n"
        : "+f"(c[0]), "+f"(c[1]), "+f"(c[2]), "+f"(c[3])
        : "r"(a[0]), "r"(a[1]), "r"(a[2]), "r"(a[3]), "r"(b[0]), "r"(b[1]));
}

__device__ __forceinline__ void cpa16(void* s, const void* g) {
    uint32_t sa = (uint32_t)__cvta_generic_to_shared(s);
    asm volatile("cp.async.cg.shared.global [%0], [%1], 16;\n" :: "r"(sa), "l"(g) : "memory");
}
#define CP_COMMIT asm volatile("cp.async.commit_group;\n" ::: "memory")
template<int W> __device__ __forceinline__ void cp_wait() {
    asm volatile("cp.async.wait_group %0;\n" :: "n"(W) : "memory");
}

// ---------------- TF32 GEMM: 64x64 tile, 4 warps, 4-stage single-sync pipeline ----------------
// C[M,Nn] = act(A[M,K] @ W[Nn,K]^T + bias + add). Requires K/16 >= 4.
#define GBK 16

__global__ void __launch_bounds__(128) tgemm(
    const float* __restrict__ A, const float* __restrict__ W,
    const float* __restrict__ bias, const float* __restrict__ add,
    float* __restrict__ C, int M, int Nn, int K, int relu) {
    __shared__ float As[4][64][20];
    __shared__ float Ws[4][64][20];

    int tid = threadIdx.x;
    int lane = tid & 31, wid = tid >> 5;
    int warp_m = wid & 1, warp_n = wid >> 1;     // 2x2 warps, 32x32 each
    int m0 = blockIdx.y * 64, n0 = blockIdx.x * 64;

    float c[2][4][4];
#pragma unroll
    for (int mt = 0; mt < 2; mt++)
#pragma unroll
        for (int nt = 0; nt < 4; nt++)
#pragma unroll
            for (int r = 0; r < 4; r++) c[mt][nt][r] = 0.f;

    int nIter = K / GBK;

    auto issue = [&](int it, int buf) {
        int k0 = it * GBK;
#pragma unroll
        for (int j = 0; j < 2; j++) {
            int cc = tid + 128 * j;
            int row = cc >> 2, ch = (cc & 3) * 4;
            cpa16(&As[buf][row][ch], &A[(long)(m0 + row) * K + k0 + ch]);
            cpa16(&Ws[buf][row][ch], &W[(long)(n0 + row) * K + k0 + ch]);
        }
    };

    issue(0, 0); CP_COMMIT;
    issue(1, 1); CP_COMMIT;
    issue(2, 2); CP_COMMIT;

    for (int i = 0; i < nIter; i++) {
        // wait until tile i has landed (pending groups: i..min(i+2, nIter-1))
        if (i < nIter - 2)      cp_wait<2>();
        else if (i == nIter - 2) cp_wait<1>();
        else                     cp_wait<0>();
        __syncthreads();   // all warps: tile i visible AND tile i-1 compute finished

        if (i + 3 < nIter) { issue(i + 3, (i + 3) & 3); CP_COMMIT; }   // overwrites buf (i-1): safe

        int buf = i & 3;
#pragma unroll
        for (int ks = 0; ks < GBK; ks += 8) {
            uint32_t a[2][4], b[4][2];
            int kk = ks + (lane & 3);
#pragma unroll
            for (int mt = 0; mt < 2; mt++) {
                int row = warp_m * 32 + mt * 16 + (lane >> 2);
                a[mt][0] = f2tf(As[buf][row][kk]);
                a[mt][1] = f2tf(As[buf][row + 8][kk]);
                a[mt][2] = f2tf(As[buf][row][kk + 4]);
                a[mt][3] = f2tf(As[buf][row + 8][kk + 4]);
            }
#pragma unroll
            for (int nt = 0; nt < 4; nt++) {
                int nc = warp_n * 32 + nt * 8 + (lane >> 2);
                b[nt][0] = f2tf(Ws[buf][nc][kk]);
                b[nt][1] = f2tf(Ws[buf][nc][kk + 4]);
            }
#pragma unroll
            for (int mt = 0; mt < 2; mt++)
#pragma unroll
                for (int nt = 0; nt < 4; nt++) mma_tf32(c[mt][nt], a[mt], b[nt]);
        }
    }

    // epilogue
#pragma unroll
    for (int mt = 0; mt < 2; mt++) {
        int rb = m0 + warp_m * 32 + mt * 16 + (lane >> 2);
#pragma unroll
        for (int nt = 0; nt < 4; nt++) {
            int cb = n0 + warp_n * 32 + nt * 8 + 2 * (lane & 3);
#pragma unroll
            for (int r = 0; r < 4; r++) {
                int mm = rb + (r >> 1) * 8;
                int nn = cb + (r & 1);
                float v = c[mt][nt][r];
                if (bias) v += bias[nn];
                if (add)  v += add[(long)mm * Nn + nn];
                if (relu) v = fmaxf(v, 0.f);
                C[(long)mm * Nn + nn] = v;
            }
        }
    }
}

// ---------------- TF32 flash attention: KV-split, 2-stage cp.async, dedicated P smem ----------------
#define KST 68
#define VST 72
#define KBUF (64 * KST)
#define VBUF (64 * VST)

__global__ void __launch_bounds__(128) flash_part(const float* __restrict__ qkv,
                                                  float* __restrict__ opart,
                                                  float* __restrict__ mpart,
                                                  float* __restrict__ lpart) {
    extern __shared__ float sm[];
    float* Ks = sm;                         // [2][64][KST]
    float* Vs = sm + 2 * KBUF;              // [2][64][VST]
    float* Ps = sm + 2 * KBUF + 2 * VBUF;   // [64][KST]  (warp-private rows)

    int tid = threadIdx.x;
    int lane = tid & 31, wid = tid >> 5;
    int q0 = blockIdx.x * 64;
    int head = blockIdx.y;
    int split = blockIdx.z;
    const int C3 = 3 * HH;
    const int qoff = head * 64, koff = HH + head * 64, voff = 2 * HH + head * 64;

    uint32_t qa[8][4];
    {
        int r = q0 + wid * 16 + (lane >> 2);
#pragma unroll
        for (int kt = 0; kt < 8; kt++) {
            int d = kt * 8 + (lane & 3);
            qa[kt][0] = f2tf(qkv[(long)r * C3 + qoff + d] * 0.125f);
            qa[kt][1] = f2tf(qkv[(long)(r + 8) * C3 + qoff + d] * 0.125f);
            qa[kt][2] = f2tf(qkv[(long)r * C3 + qoff + d + 4] * 0.125f);
            qa[kt][3] = f2tf(qkv[(long)(r + 8) * C3 + qoff + d + 4] * 0.125f);
        }
    }

    float m0 = -1e30f, m1 = -1e30f, l0 = 0.f, l1 = 0.f;
    float o[8][4];
#pragma unroll
    for (int nt = 0; nt < 8; nt++)
#pragma unroll
        for (int r = 0; r < 4; r++) o[nt][r] = 0.f;

    int kbase = split * (NN / SPLITS);
    const int nIter = (NN / SPLITS) / 64;

    auto issue = [&](int it, int buf) {
        int k0 = kbase + it * 64;
#pragma unroll
        for (int j = 0; j < 8; j++) {
            int cc = tid + 128 * j;
            int key = cc >> 4, ch = (cc & 15) * 4;
            cpa16(&Ks[buf * KBUF + key * KST + ch], &qkv[(long)(k0 + key) * C3 + koff + ch]);
            cpa16(&Vs[buf * VBUF + key * VST + ch], &qkv[(long)(k0 + key) * C3 + voff + ch]);
        }
    };

    issue(0, 0); CP_COMMIT;
    int cur = 0;
    for (int i = 0; i < nIter; i++) {
        if (i + 1 < nIter) { issue(i + 1, cur ^ 1); CP_COMMIT; cp_wait<1>(); }
        else cp_wait<0>();
        __syncthreads();   // tile i visible to all warps

        const float* Kc = Ks + cur * KBUF;
        const float* Vc = Vs + cur * VBUF;

        // S = Q K^T
        float s[8][4];
#pragma unroll
        for (int nt = 0; nt < 8; nt++)
#pragma unroll
            for (int r = 0; r < 4; r++) s[nt][r] = 0.f;
#pragma unroll
        for (int kt = 0; kt < 8; kt++) {
            int kk = kt * 8 + (lane & 3);
            uint32_t b[2];
#pragma unroll
            for (int nt = 0; nt < 8; nt++) {
                int key = nt * 8 + (lane >> 2);
                b[0] = f2tf(Kc[key * KST + kk]);
                b[1] = f2tf(Kc[key * KST + kk + 4]);
                mma_tf32(s[nt], qa[kt], b);
            }
        }

        // online softmax
        float mx0 = -1e30f, mx1 = -1e30f;
#pragma unroll
        for (int nt = 0; nt < 8; nt++) {
            mx0 = fmaxf(mx0, fmaxf(s[nt][0], s[nt][1]));
            mx1 = fmaxf(mx1, fmaxf(s[nt][2], s[nt][3]));
        }
#pragma unroll
        for (int off = 1; off <= 2; off <<= 1) {
            mx0 = fmaxf(mx0, __shfl_xor_sync(0xffffffffu, mx0, off));
            mx1 = fmaxf(mx1, __shfl_xor_sync(0xffffffffu, mx1, off));
        }
        float mn0 = fmaxf(m0, mx0), mn1 = fmaxf(m1, mx1);
        float sum0 = 0.f, sum1 = 0.f;
#pragma unroll
        for (int nt = 0; nt < 8; nt++) {
            s[nt][0] = __expf(s[nt][0] - mn0);
            s[nt][1] = __expf(s[nt][1] - mn0);
            s[nt][2] = __expf(s[nt][2] - mn1);
            s[nt][3] = __expf(s[nt][3] - mn1);
            sum0 += s[nt][0] + s[nt][1];
            sum1 += s[nt][2] + s[nt][3];
        }
#pragma unroll
        for (int off = 1; off <= 2; off <<= 1) {
            sum0 += __shfl_xor_sync(0xffffffffu, sum0, off);
            sum1 += __shfl_xor_sync(0xffffffffu, sum1, off);
        }
        float e0 = __expf(m0 - mn0), e1 = __expf(m1 - mn1);
        l0 = l0 * e0 + sum0;
        l1 = l1 * e1 + sum1;
        m0 = mn0; m1 = mn1;
#pragma unroll
        for (int nt = 0; nt < 8; nt++) {
            o[nt][0] *= e0; o[nt][1] *= e0;
            o[nt][2] *= e1; o[nt][3] *= e1;
        }

        // P into dedicated smem (warp-private rows -> no block barrier)
        {
            int r = wid * 16 + (lane >> 2);
#pragma unroll
            for (int nt = 0; nt < 8; nt++) {
                int cb = nt * 8 + 2 * (lane & 3);
                Ps[r * KST + cb]           = __uint_as_float(f2tf(s[nt][0]));
                Ps[r * KST + cb + 1]       = __uint_as_float(f2tf(s[nt][1]));
                Ps[(r + 8) * KST + cb]     = __uint_as_float(f2tf(s[nt][2]));
                Ps[(r + 8) * KST + cb + 1] = __uint_as_float(f2tf(s[nt][3]));
            }
        }
        __syncwarp();

        // O += P V
#pragma unroll
        for (int kt = 0; kt < 8; kt++) {
            int r = wid * 16 + (lane >> 2);
            int kk = kt * 8 + (lane & 3);
            uint32_t a[4];
            a[0] = __float_as_uint(Ps[r * KST + kk]);
            a[1] = __float_as_uint(Ps[(r + 8) * KST + kk]);
            a[2] = __float_as_uint(Ps[r * KST + kk + 4]);
            a[3] = __float_as_uint(Ps[(r + 8) * KST + kk + 4]);
            uint32_t b[2];
#pragma unroll
            for (int nt = 0; nt < 8; nt++) {
                int dd = nt * 8 + (lane >> 2);
                b[0] = f2tf(Vc[kk * VST + dd]);
                b[1] = f2tf(Vc[(kk + 4) * VST + dd]);
                mma_tf32(o[nt], a, b);
            }
        }
        __syncthreads();   // Kc/Vc readers done before next issue overwrites
        cur ^= 1;
    }

    int r = q0 + wid * 16 + (lane >> 2);
    float* ob = opart + (long)split * NN * HH;
#pragma unroll
    for (int nt = 0; nt < 8; nt++) {
        int cb = head * 64 + nt * 8 + 2 * (lane & 3);
        ob[(long)r * HH + cb]           = o[nt][0];
        ob[(long)r * HH + cb + 1]       = o[nt][1];
        ob[(long)(r + 8) * HH + cb]     = o[nt][2];
        ob[(long)(r + 8) * HH + cb + 1] = o[nt][3];
    }
    if ((lane & 3) == 0) {
        int base = (split * 4 + head) * NN;
        mpart[base + r] = m0;     lpart[base + r] = l0;
        mpart[base + r + 8] = m1; lpart[base + r + 8] = l1;
    }
}

__global__ void flash_merge(const float* __restrict__ opart, const float* __restrict__ mpart,
                            const float* __restrict__ lpart, float* __restrict__ out) {
    int idx = blockIdx.x * blockDim.x + threadIdx.x;
    if (idx >= NN * HH) return;
    int row = idx >> 8, c = idx & 255, head = c >> 6;
    float mv[SPLITS], lv[SPLITS];
    float mmax = -1e30f;
#pragma unroll
    for (int s = 0; s < SPLITS; s++) {
        mv[s] = mpart[(s * 4 + head) * NN + row];
        lv[s] = lpart[(s * 4 + head) * NN + row];
        mmax = fmaxf(mmax, mv[s]);
    }
    float num = 0.f, den = 0.f;
#pragma unroll
    for (int s = 0; s < SPLITS; s++) {
        float w = __expf(mv[s] - mmax);
        num += opart[(long)s * NN * HH + idx] * w;
        den += lv[s] * w;
    }
    out[idx] = num / den;
}

// ---------------- GCN helpers ----------------
__global__ void deg_init(float* deg, int n) {
    int i = blockIdx.x * blockDim.x + threadIdx.x;
    if (i < n) deg[i] = 1.f;
}
__global__ void deg_count(const int* __restrict__ dst, float* deg, int e) {
    int i = blockIdx.x * blockDim.x + threadIdx.x;
    if (i < e) atomicAdd(&deg[dst[i]], 1.f);
}
__global__ void dinv_kernel(const float* __restrict__ deg, float* dinv, int n) {
    int i = blockIdx.x * blockDim.x + threadIdx.x;
    if (i < n) dinv[i] = rsqrtf(deg[i]);
}

__global__ void gcn_scatter(const int* __restrict__ src, const int* __restrict__ dst,
                            const float* __restrict__ dinv, const float* __restrict__ xlin,
                            float* __restrict__ agg, int e) {
    int w = (blockIdx.x * blockDim.x + threadIdx.x) >> 5;
    int lane = threadIdx.x & 31;
    if (w >= e) return;
    int s = src[w], d = dst[w];
    float coef = dinv[s] * dinv[d];
    const float* xs = xlin + (long)s * HH;
    float* ad = agg + (long)d * HH;
#pragma unroll
    for (int k = 0; k < HH / 32; k++)
        atomicAdd(&ad[lane + 32 * k], xs[lane + 32 * k] * coef);
}

__global__ void combine(const float* __restrict__ agg, const float* __restrict__ xlin,
                        const float* __restrict__ dinv, const float* __restrict__ gcn_b,
                        const float* __restrict__ proj, const float* __restrict__ h,
                        float* __restrict__ out, int total) {
    int idx = blockIdx.x * blockDim.x + threadIdx.x;
    if (idx >= total) return;
    int i = idx >> 8, c = idx & 255;
    float dv = dinv[i];
    out[idx] = agg[idx] + xlin[idx] * dv * dv + gcn_b[c] + proj[idx] + 2.f * h[idx];
}

// ---------------- tiled symmetrize ----------------
__global__ void __launch_bounds__(256) symmetrize(float* __restrict__ o) {
    int ti = blockIdx.y, tj = blockIdx.x;
    if (tj < ti) return;
    __shared__ float As[64][65];
    __shared__ float Bs[64][65];
    int tid = threadIdx.x;
    int r = tid >> 2, c0 = (tid & 3) * 16;
    long base_a = (long)ti * 64 * NN + tj * 64;
    long base_b = (long)tj * 64 * NN + ti * 64;

#pragma unroll
    for (int j = 0; j < 16; j += 4) {
        float4 va = *(const float4*)&o[base_a + (long)r * NN + c0 + j];
        float4 vb = *(const float4*)&o[base_b + (long)r * NN + c0 + j];
        As[r][c0 + j] = va.x; As[r][c0 + j + 1] = va.y;
        As[r][c0 + j + 2] = va.z; As[r][c0 + j + 3] = va.w;
        Bs[r][c0 + j] = vb.x; Bs[r][c0 + j + 1] = vb.y;
        Bs[r][c0 + j + 2] = vb.z; Bs[r][c0 + j + 3] = vb.w;
    }
    __syncthreads();

#pragma unroll
    for (int j = 0; j < 16; j += 4) {
        float4 wa, wb;
        wa.x = 0.5f * (As[r][c0 + j]     + Bs[c0 + j][r]);
        wa.y = 0.5f * (As[r][c0 + j + 1] + Bs[c0 + j + 1][r]);
        wa.z = 0.5f * (As[r][c0 + j + 2] + Bs[c0 + j + 2][r]);
        wa.w = 0.5f * (As[r][c0 + j + 3] + Bs[c0 + j + 3][r]);
        *(float4*)&o[base_a + (long)r * NN + c0 + j] = wa;
        if (ti != tj) {
            wb.x = 0.5f * (Bs[r][c0 + j]     + As[c0 + j][r]);
            wb.y = 0.5f * (Bs[r][c0 + j + 1] + As[c0 + j + 1][r]);
            wb.z = 0.5f * (Bs[r][c0 + j + 2] + As[c0 + j + 2][r]);
            wb.w = 0.5f * (Bs[r][c0 + j + 3] + As[c0 + j + 3][r]);
            *(float4*)&o[base_b + (long)r * NN + c0 + j] = wb;
        }
    }
}

// ---------------- launch ----------------
extern "C" void kernel_launch(void* const* d_in, const int* in_sizes, int n_in,
                              void* d_out, int out_size) {
    const float* x      = (const float*)d_in[0];
    const int*   ei     = (const int*)d_in[1];
    const float* pre_w  = (const float*)d_in[2];
    const float* pre_b  = (const float*)d_in[3];
    const float* mlp_w1 = (const float*)d_in[24];
    const float* mlp_b1 = (const float*)d_in[25];
    const float* mlp_w2 = (const float*)d_in[26];
    const float* mlp_b2 = (const float*)d_in[27];

    float *h, *xlin, *qkv, *attn, *proj, *agg, *outb, *ffn, *hid, *deg, *dinv;
    float *opart, *mpart, *lpart;
    cudaGetSymbolAddress((void**)&h,    g_h);
    cudaGetSymbolAddress((void**)&xlin, g_xlin);
    cudaGetSymbolAddress((void**)&qkv,  g_qkv);
    cudaGetSymbolAddress((void**)&attn, g_attn);
    cudaGetSymbolAddress((void**)&proj, g_proj);
    cudaGetSymbolAddress((void**)&agg,  g_agg);
    cudaGetSymbolAddress((void**)&outb, g_out);
    cudaGetSymbolAddress((void**)&ffn,  g_ffn);
    cudaGetSymbolAddress((void**)&hid,  g_hid);
    cudaGetSymbolAddress((void**)&deg,  g_deg);
    cudaGetSymbolAddress((void**)&dinv, g_dinv);
    cudaGetSymbolAddress((void**)&opart, g_opart);
    cudaGetSymbolAddress((void**)&mpart, g_mpart);
    cudaGetSymbolAddress((void**)&lpart, g_lpart);

    const int flash_smem = (2 * KBUF + 2 * VBUF + 64 * KST) * (int)sizeof(float);  // 89088
    cudaFuncSetAttribute(flash_part, cudaFuncAttributeMaxDynamicSharedMemorySize, flash_smem);

    deg_init<<<(NN + 255) / 256, 256>>>(deg, NN);
    deg_count<<<(EE + 255) / 256, 256>>>(ei + EE, deg, EE);
    dinv_kernel<<<(NN + 255) / 256, 256>>>(deg, dinv, NN);

    // pre: h = relu(x @ pre_w^T + pre_b)
    tgemm<<<dim3(HH / 64, NN / 64), 128>>>(x, pre_w, pre_b, nullptr, h, NN, HH, 128, 1);

    for (int L = 0; L < 2; L++) {
        int base = 4 + L * 10;
        const float* gcn_w  = (const float*)d_in[base + 0];
        const float* gcn_b  = (const float*)d_in[base + 1];
        const float* in_w   = (const float*)d_in[base + 2];
        const float* in_b   = (const float*)d_in[base + 3];
        const float* out_w  = (const float*)d_in[base + 4];
        const float* out_b  = (const float*)d_in[base + 5];
        const float* ffn_w1 = (const float*)d_in[base + 6];
        const float* ffn_b1 = (const float*)d_in[base + 7];
        const float* ffn_w2 = (const float*)d_in[base + 8];
        const float* ffn_b2 = (const float*)d_in[base + 9];

        tgemm<<<dim3(HH / 64, NN / 64), 128>>>(h, gcn_w, nullptr, nullptr, xlin, NN, HH, HH, 0);
        tgemm<<<dim3(3 * HH / 64, NN / 64), 128>>>(h, in_w, in_b, nullptr, qkv, NN, 3 * HH, HH, 0);
        flash_part<<<dim3(NN / 64, 4, SPLITS), 128, flash_smem>>>(qkv, opart, mpart, lpart);
        flash_merge<<<(NN * HH) / 256, 256>>>(opart, mpart, lpart, attn);
        tgemm<<<dim3(HH / 64, NN / 64), 128>>>(attn, out_w, out_b, nullptr, proj, NN, HH, HH, 0);
        cudaMemsetAsync(agg, 0, (size_t)NN * HH * sizeof(float));
        gcn_scatter<<<(EE * 32) / 256, 256>>>(ei, ei + EE, dinv, xlin, agg, EE);
        combine<<<(NN * HH) / 256, 256>>>(agg, xlin, dinv, gcn_b, proj, h, outb, NN * HH);
        tgemm<<<dim3(2 * HH / 64, NN / 64), 128>>>(outb, ffn_w1, ffn_b1, nullptr, ffn, NN, 2 * HH, HH, 1);
        tgemm<<<dim3(HH / 64, NN / 64), 128>>>(ffn, ffn_w2, ffn_b2, outb, h, NN, HH, 2 * HH, 1);
    }

    // head
    tgemm<<<dim3(HH / 64, NN / 64), 128>>>(h, mlp_w1, mlp_b1, nullptr, hid, NN, HH, HH, 1);
    tgemm<<<dim3(NN / 64, NN / 64), 128>>>(hid, mlp_w2, mlp_b2, nullptr, (float*)d_out, NN, NN, HH, 0);
    symmetrize<<<dim3(NN / 64, NN / 64), 256>>>((float*)d_out);
}

// round 7
// speedup vs baseline: 1.1028x; 1.1028x over previous
#include <cuda_runtime.h>
#include <cuda_bf16.h>
#include <stdint.h>
#include <math.h>

#define NN 4096
#define HH 256
#define EE 65536
#define SPLITS 8

// ---------------- device scratch ----------------
__device__ float g_h[NN * HH];
__device__ float g_xlin[NN * HH];
__device__ float g_qkv[NN * 3 * HH];
__device__ float g_attn[NN * HH];
__device__ float g_proj[NN * HH];
__device__ float g_agg[NN * HH];
__device__ float g_out[NN * HH];
__device__ float g_ffn[NN * 2 * HH];
__device__ float g_hid[NN * HH];
__device__ float g_deg[NN];
__device__ float g_dinv[NN];
__device__ float g_opart[SPLITS * NN * HH];
__device__ float g_mpart[SPLITS * 4 * NN];
__device__ float g_lpart[SPLITS * 4 * NN];

// ---------------- helpers ----------------
__device__ __forceinline__ uint32_t f2tf(float f) {
    uint32_t u;
    asm("cvt.rna.tf32.f32 %0, %1;" : "=r"(u) : "f"(f));
    return u;
}

__device__ __forceinline__ void mma_tf32(float c[4], const uint32_t a[4], const uint32_t b[2]) {
    asm volatile(
        "mma.sync.aligned.m16n8k8.row.col.f32.tf32.tf32.f32 "
        "{%0,%1,%2,%3},{%4,%5,%6,%7},{%8,%9},{%0,%1,%2,%3};\n"
        : "+f"(c[0]), "+f"(c[1]), "+f"(c[2]), "+f"(c[3])
        : "r"(a[0]), "r"(a[1]), "r"(a[2]), "r"(a[3]), "r"(b[0]), "r"(b[1]));
}

__device__ __forceinline__ void cpa16(void* s, const void* g) {
    uint32_t sa = (uint32_t)__cvta_generic_to_shared(s);
    asm volatile("cp.async.cg.shared.global [%0], [%1], 16;\n" :: "r"(sa), "l"(g) : "memory");
}
#define CP_COMMIT asm volatile("cp.async.commit_group;\n" ::: "memory")
template<int W> __device__ __forceinline__ void cp_wait() {
    asm volatile("cp.async.wait_group %0;\n" :: "n"(W) : "memory");
}

// ---------------- TF32 GEMM: 64x64 tile, 8 warps (warp tile 32x16), 3-stage ----------------
// C[M,Nn] = act(A[M,K] @ W[Nn,K]^T + bias + add). Requires K % 16 == 0, K/16 >= 2.
#define GBK 16

__global__ void __launch_bounds__(256) tgemm(
    const float* __restrict__ A, const float* __restrict__ W,
    const float* __restrict__ bias, const float* __restrict__ add,
    float* __restrict__ C, int M, int Nn, int K, int relu) {
    __shared__ float As[3][64][20];   // stride 20: conflict-free fragment reads
    __shared__ float Ws[3][64][20];

    int tid = threadIdx.x;
    int lane = tid & 31, wid = tid >> 5;
    int warp_m = wid & 1, warp_n = wid >> 1;     // 2x4 warps, 32x16 per warp
    int m0 = blockIdx.y * 64, n0 = blockIdx.x * 64;

    float c[2][2][4];
#pragma unroll
    for (int mt = 0; mt < 2; mt++)
#pragma unroll
        for (int nt = 0; nt < 2; nt++)
#pragma unroll
            for (int r = 0; r < 4; r++) c[mt][nt][r] = 0.f;

    int nIter = K / GBK;

    auto issue = [&](int it, int buf) {
        int k0 = it * GBK;
        int row = tid >> 2, ch = (tid & 3) * 4;   // 256 threads cover 64x16 exactly
        cpa16(&As[buf][row][ch], &A[(long)(m0 + row) * K + k0 + ch]);
        cpa16(&Ws[buf][row][ch], &W[(long)(n0 + row) * K + k0 + ch]);
    };

    issue(0, 0); CP_COMMIT;
    issue(1, 1); CP_COMMIT;

    for (int i = 0; i < nIter; i++) {
        int buf = i % 3;
        if (i + 2 < nIter) { issue(i + 2, (i + 2) % 3); CP_COMMIT; cp_wait<2>(); }
        else if (i + 1 < nIter) cp_wait<1>();
        else cp_wait<0>();
        __syncthreads();

#pragma unroll
        for (int ks = 0; ks < GBK; ks += 8) {
            uint32_t a[2][4], b[2][2];
            int kk = ks + (lane & 3);
#pragma unroll
            for (int mt = 0; mt < 2; mt++) {
                int row = warp_m * 32 + mt * 16 + (lane >> 2);
                a[mt][0] = f2tf(As[buf][row][kk]);
                a[mt][1] = f2tf(As[buf][row + 8][kk]);
                a[mt][2] = f2tf(As[buf][row][kk + 4]);
                a[mt][3] = f2tf(As[buf][row + 8][kk + 4]);
            }
#pragma unroll
            for (int nt = 0; nt < 2; nt++) {
                int nc = warp_n * 16 + nt * 8 + (lane >> 2);
                b[nt][0] = f2tf(Ws[buf][nc][kk]);
                b[nt][1] = f2tf(Ws[buf][nc][kk + 4]);
            }
#pragma unroll
            for (int mt = 0; mt < 2; mt++)
#pragma unroll
                for (int nt = 0; nt < 2; nt++) mma_tf32(c[mt][nt], a[mt], b[nt]);
        }
        __syncthreads();   // protect buf before re-issue
    }

    // epilogue
#pragma unroll
    for (int mt = 0; mt < 2; mt++) {
        int rb = m0 + warp_m * 32 + mt * 16 + (lane >> 2);
#pragma unroll
        for (int nt = 0; nt < 2; nt++) {
            int cb = n0 + warp_n * 16 + nt * 8 + 2 * (lane & 3);
#pragma unroll
            for (int r = 0; r < 4; r++) {
                int mm = rb + (r >> 1) * 8;
                int nn = cb + (r & 1);
                float v = c[mt][nt][r];
                if (bias) v += bias[nn];
                if (add)  v += add[(long)mm * Nn + nn];
                if (relu) v = fmaxf(v, 0.f);
                C[(long)mm * Nn + nn] = v;
            }
        }
    }
}

// ---------------- TF32 flash attention, KV-split + cp.async (round-5 config) ----------------
#define KST 68
#define VST 72
#define KBUF (64 * KST)
#define VBUF (64 * VST)

__global__ void __launch_bounds__(128) flash_part(const float* __restrict__ qkv,
                                                  float* __restrict__ opart,
                                                  float* __restrict__ mpart,
                                                  float* __restrict__ lpart) {
    extern __shared__ float sm[];
    float* Ks = sm;                 // [2][64][KST]; reused as P after S-matmul
    float* Vs = sm + 2 * KBUF;      // [2][64][VST]

    int tid = threadIdx.x;
    int lane = tid & 31, wid = tid >> 5;
    int q0 = blockIdx.x * 64;
    int head = blockIdx.y;
    int split = blockIdx.z;
    const int C3 = 3 * HH;
    const int qoff = head * 64, koff = HH + head * 64, voff = 2 * HH + head * 64;

    uint32_t qa[8][4];
    {
        int r = q0 + wid * 16 + (lane >> 2);
#pragma unroll
        for (int kt = 0; kt < 8; kt++) {
            int d = kt * 8 + (lane & 3);
            qa[kt][0] = f2tf(qkv[(long)r * C3 + qoff + d] * 0.125f);
            qa[kt][1] = f2tf(qkv[(long)(r + 8) * C3 + qoff + d] * 0.125f);
            qa[kt][2] = f2tf(qkv[(long)r * C3 + qoff + d + 4] * 0.125f);
            qa[kt][3] = f2tf(qkv[(long)(r + 8) * C3 + qoff + d + 4] * 0.125f);
        }
    }

    float m0 = -1e30f, m1 = -1e30f, l0 = 0.f, l1 = 0.f;
    float o[8][4];
#pragma unroll
    for (int nt = 0; nt < 8; nt++)
#pragma unroll
        for (int r = 0; r < 4; r++) o[nt][r] = 0.f;

    int kbase = split * (NN / SPLITS);
    const int nIter = (NN / SPLITS) / 64;

    auto issue = [&](int it, int buf) {
        int k0 = kbase + it * 64;
#pragma unroll
        for (int j = 0; j < 8; j++) {
            int cc = tid + 128 * j;
            int key = cc >> 4, ch = (cc & 15) * 4;
            cpa16(&Ks[buf * KBUF + key * KST + ch], &qkv[(long)(k0 + key) * C3 + koff + ch]);
            cpa16(&Vs[buf * VBUF + key * VST + ch], &qkv[(long)(k0 + key) * C3 + voff + ch]);
        }
    };

    issue(0, 0); CP_COMMIT;
    int cur = 0;
    for (int i = 0; i < nIter; i++) {
        if (i + 1 < nIter) { issue(i + 1, cur ^ 1); CP_COMMIT; cp_wait<1>(); }
        else cp_wait<0>();
        __syncthreads();

        float* Kc = Ks + cur * KBUF;
        const float* Vc = Vs + cur * VBUF;

        float s[8][4];
#pragma unroll
        for (int nt = 0; nt < 8; nt++)
#pragma unroll
            for (int r = 0; r < 4; r++) s[nt][r] = 0.f;
#pragma unroll
        for (int kt = 0; kt < 8; kt++) {
            int kk = kt * 8 + (lane & 3);
            uint32_t b[2];
#pragma unroll
            for (int nt = 0; nt < 8; nt++) {
                int key = nt * 8 + (lane >> 2);
                b[0] = f2tf(Kc[key * KST + kk]);
                b[1] = f2tf(Kc[key * KST + kk + 4]);
                mma_tf32(s[nt], qa[kt], b);
            }
        }

        float mx0 = -1e30f, mx1 = -1e30f;
#pragma unroll
        for (int nt = 0; nt < 8; nt++) {
            mx0 = fmaxf(mx0, fmaxf(s[nt][0], s[nt][1]));
            mx1 = fmaxf(mx1, fmaxf(s[nt][2], s[nt][3]));
        }
#pragma unroll
        for (int off = 1; off <= 2; off <<= 1) {
            mx0 = fmaxf(mx0, __shfl_xor_sync(0xffffffffu, mx0, off));
            mx1 = fmaxf(mx1, __shfl_xor_sync(0xffffffffu, mx1, off));
        }
        float mn0 = fmaxf(m0, mx0), mn1 = fmaxf(m1, mx1);
        float sum0 = 0.f, sum1 = 0.f;
#pragma unroll
        for (int nt = 0; nt < 8; nt++) {
            s[nt][0] = __expf(s[nt][0] - mn0);
            s[nt][1] = __expf(s[nt][1] - mn0);
            s[nt][2] = __expf(s[nt][2] - mn1);
            s[nt][3] = __expf(s[nt][3] - mn1);
            sum0 += s[nt][0] + s[nt][1];
            sum1 += s[nt][2] + s[nt][3];
        }
#pragma unroll
        for (int off = 1; off <= 2; off <<= 1) {
            sum0 += __shfl_xor_sync(0xffffffffu, sum0, off);
            sum1 += __shfl_xor_sync(0xffffffffu, sum1, off);
        }
        float e0 = __expf(m0 - mn0), e1 = __expf(m1 - mn1);
        l0 = l0 * e0 + sum0;
        l1 = l1 * e1 + sum1;
        m0 = mn0; m1 = mn1;
#pragma unroll
        for (int nt = 0; nt < 8; nt++) {
            o[nt][0] *= e0; o[nt][1] *= e0;
            o[nt][2] *= e1; o[nt][3] *= e1;
        }

        __syncthreads();   // Kc readers done -> reuse as P

        {
            int r = wid * 16 + (lane >> 2);
#pragma unroll
            for (int nt = 0; nt < 8; nt++) {
                int cb = nt * 8 + 2 * (lane & 3);
                Kc[r * KST + cb]           = __uint_as_float(f2tf(s[nt][0]));
                Kc[r * KST + cb + 1]       = __uint_as_float(f2tf(s[nt][1]));
                Kc[(r + 8) * KST + cb]     = __uint_as_float(f2tf(s[nt][2]));
                Kc[(r + 8) * KST + cb + 1] = __uint_as_float(f2tf(s[nt][3]));
            }
        }
        __syncwarp();

#pragma unroll
        for (int kt = 0; kt < 8; kt++) {
            int r = wid * 16 + (lane >> 2);
            int kk = kt * 8 + (lane & 3);
            uint32_t a[4];
            a[0] = __float_as_uint(Kc[r * KST + kk]);
            a[1] = __float_as_uint(Kc[(r + 8) * KST + kk]);
            a[2] = __float_as_uint(Kc[r * KST + kk + 4]);
            a[3] = __float_as_uint(Kc[(r + 8) * KST + kk + 4]);
            uint32_t b[2];
#pragma unroll
            for (int nt = 0; nt < 8; nt++) {
                int dd = nt * 8 + (lane >> 2);
                b[0] = f2tf(Vc[kk * VST + dd]);
                b[1] = f2tf(Vc[(kk + 4) * VST + dd]);
                mma_tf32(o[nt], a, b);
            }
        }
        __syncthreads();
        cur ^= 1;
    }

    int r = q0 + wid * 16 + (lane >> 2);
    float* ob = opart + (long)split * NN * HH;
#pragma unroll
    for (int nt = 0; nt < 8; nt++) {
        int cb = head * 64 + nt * 8 + 2 * (lane & 3);
        ob[(long)r * HH + cb]           = o[nt][0];
        ob[(long)r * HH + cb + 1]       = o[nt][1];
        ob[(long)(r + 8) * HH + cb]     = o[nt][2];
        ob[(long)(r + 8) * HH + cb + 1] = o[nt][3];
    }
    if ((lane & 3) == 0) {
        int base = (split * 4 + head) * NN;
        mpart[base + r] = m0;     lpart[base + r] = l0;
        mpart[base + r + 8] = m1; lpart[base + r + 8] = l1;
    }
}

__global__ void flash_merge(const float* __restrict__ opart, const float* __restrict__ mpart,
                            const float* __restrict__ lpart, float* __restrict__ out) {
    int idx = blockIdx.x * blockDim.x + threadIdx.x;
    if (idx >= NN * HH) return;
    int row = idx >> 8, c = idx & 255, head = c >> 6;
    float mv[SPLITS], lv[SPLITS];
    float mmax = -1e30f;
#pragma unroll
    for (int s = 0; s < SPLITS; s++) {
        mv[s] = mpart[(s * 4 + head) * NN + row];
        lv[s] = lpart[(s * 4 + head) * NN + row];
        mmax = fmaxf(mmax, mv[s]);
    }
    float num = 0.f, den = 0.f;
#pragma unroll
    for (int s = 0; s < SPLITS; s++) {
        float w = __expf(mv[s] - mmax);
        num += opart[(long)s * NN * HH + idx] * w;
        den += lv[s] * w;
    }
    out[idx] = num / den;
}

// ---------------- GCN helpers ----------------
__global__ void deg_init(float* deg, int n) {
    int i = blockIdx.x * blockDim.x + threadIdx.x;
    if (i < n) deg[i] = 1.f;
}
__global__ void deg_count(const int* __restrict__ dst, float* deg, int e) {
    int i = blockIdx.x * blockDim.x + threadIdx.x;
    if (i < e) atomicAdd(&deg[dst[i]], 1.f);
}
__global__ void dinv_kernel(const float* __restrict__ deg, float* dinv, int n) {
    int i = blockIdx.x * blockDim.x + threadIdx.x;
    if (i < n) dinv[i] = rsqrtf(deg[i]);
}

__global__ void gcn_scatter(const int* __restrict__ src, const int* __restrict__ dst,
                            const float* __restrict__ dinv, const float* __restrict__ xlin,
                            float* __restrict__ agg, int e) {
    int w = (blockIdx.x * blockDim.x + threadIdx.x) >> 5;
    int lane = threadIdx.x & 31;
    if (w >= e) return;
    int s = src[w], d = dst[w];
    float coef = dinv[s] * dinv[d];
    const float* xs = xlin + (long)s * HH;
    float* ad = agg + (long)d * HH;
#pragma unroll
    for (int k = 0; k < HH / 32; k++)
        atomicAdd(&ad[lane + 32 * k], xs[lane + 32 * k] * coef);
}

__global__ void combine(const float* __restrict__ agg, const float* __restrict__ xlin,
                        const float* __restrict__ dinv, const float* __restrict__ gcn_b,
                        const float* __restrict__ proj, const float* __restrict__ h,
                        float* __restrict__ out, int total) {
    int idx = blockIdx.x * blockDim.x + threadIdx.x;
    if (idx >= total) return;
    int i = idx >> 8, c = idx & 255;
    float dv = dinv[i];
    out[idx] = agg[idx] + xlin[idx] * dv * dv + gcn_b[c] + proj[idx] + 2.f * h[idx];
}

// ---------------- tiled symmetrize ----------------
__global__ void __launch_bounds__(256) symmetrize(float* __restrict__ o) {
    int ti = blockIdx.y, tj = blockIdx.x;
    if (tj < ti) return;
    __shared__ float As[64][65];
    __shared__ float Bs[64][65];
    int tid = threadIdx.x;
    int r = tid >> 2, c0 = (tid & 3) * 16;
    long base_a = (long)ti * 64 * NN + tj * 64;
    long base_b = (long)tj * 64 * NN + ti * 64;

#pragma unroll
    for (int j = 0; j < 16; j += 4) {
        float4 va = *(const float4*)&o[base_a + (long)r * NN + c0 + j];
        float4 vb = *(const float4*)&o[base_b + (long)r * NN + c0 + j];
        As[r][c0 + j] = va.x; As[r][c0 + j + 1] = va.y;
        As[r][c0 + j + 2] = va.z; As[r][c0 + j + 3] = va.w;
        Bs[r][c0 + j] = vb.x; Bs[r][c0 + j + 1] = vb.y;
        Bs[r][c0 + j + 2] = vb.z; Bs[r][c0 + j + 3] = vb.w;
    }
    __syncthreads();

#pragma unroll
    for (int j = 0; j < 16; j += 4) {
        float4 wa, wb;
        wa.x = 0.5f * (As[r][c0 + j]     + Bs[c0 + j][r]);
        wa.y = 0.5f * (As[r][c0 + j + 1] + Bs[c0 + j + 1][r]);
        wa.z = 0.5f * (As[r][c0 + j + 2] + Bs[c0 + j + 2][r]);
        wa.w = 0.5f * (As[r][c0 + j + 3] + Bs[c0 + j + 3][r]);
        *(float4*)&o[base_a + (long)r * NN + c0 + j] = wa;
        if (ti != tj) {
            wb.x = 0.5f * (Bs[r][c0 + j]     + As[c0 + j][r]);
            wb.y = 0.5f * (Bs[r][c0 + j + 1] + As[c0 + j + 1][r]);
            wb.z = 0.5f * (Bs[r][c0 + j + 2] + As[c0 + j + 2][r]);
            wb.w = 0.5f * (Bs[r][c0 + j + 3] + As[c0 + j + 3][r]);
            *(float4*)&o[base_b + (long)r * NN + c0 + j] = wb;
        }
    }
}

// ---------------- launch ----------------
extern "C" void kernel_launch(void* const* d_in, const int* in_sizes, int n_in,
                              void* d_out, int out_size) {
    const float* x      = (const float*)d_in[0];
    const int*   ei     = (const int*)d_in[1];
    const float* pre_w  = (const float*)d_in[2];
    const float* pre_b  = (const float*)d_in[3];
    const float* mlp_w1 = (const float*)d_in[24];
    const float* mlp_b1 = (const float*)d_in[25];
    const float* mlp_w2 = (const float*)d_in[26];
    const float* mlp_b2 = (const float*)d_in[27];

    float *h, *xlin, *qkv, *attn, *proj, *agg, *outb, *ffn, *hid, *deg, *dinv;
    float *opart, *mpart, *lpart;
    cudaGetSymbolAddress((void**)&h,    g_h);
    cudaGetSymbolAddress((void**)&xlin, g_xlin);
    cudaGetSymbolAddress((void**)&qkv,  g_qkv);
    cudaGetSymbolAddress((void**)&attn, g_attn);
    cudaGetSymbolAddress((void**)&proj, g_proj);
    cudaGetSymbolAddress((void**)&agg,  g_agg);
    cudaGetSymbolAddress((void**)&outb, g_out);
    cudaGetSymbolAddress((void**)&ffn,  g_ffn);
    cudaGetSymbolAddress((void**)&hid,  g_hid);
    cudaGetSymbolAddress((void**)&deg,  g_deg);
    cudaGetSymbolAddress((void**)&dinv, g_dinv);
    cudaGetSymbolAddress((void**)&opart, g_opart);
    cudaGetSymbolAddress((void**)&mpart, g_mpart);
    cudaGetSymbolAddress((void**)&lpart, g_lpart);

    const int flash_smem = (2 * KBUF + 2 * VBUF) * (int)sizeof(float);  // 71680
    cudaFuncSetAttribute(flash_part, cudaFuncAttributeMaxDynamicSharedMemorySize, flash_smem);

    deg_init<<<(NN + 255) / 256, 256>>>(deg, NN);
    deg_count<<<(EE + 255) / 256, 256>>>(ei + EE, deg, EE);
    dinv_kernel<<<(NN + 255) / 256, 256>>>(deg, dinv, NN);

    // pre: h = relu(x @ pre_w^T + pre_b)
    tgemm<<<dim3(HH / 64, NN / 64), 256>>>(x, pre_w, pre_b, nullptr, h, NN, HH, 128, 1);

    for (int L = 0; L < 2; L++) {
        int base = 4 + L * 10;
        const float* gcn_w  = (const float*)d_in[base + 0];
        const float* gcn_b  = (const float*)d_in[base + 1];
        const float* in_w   = (const float*)d_in[base + 2];
        const float* in_b   = (const float*)d_in[base + 3];
        const float* out_w  = (const float*)d_in[base + 4];
        const float* out_b  = (const float*)d_in[base + 5];
        const float* ffn_w1 = (const float*)d_in[base + 6];
        const float* ffn_b1 = (const float*)d_in[base + 7];
        const float* ffn_w2 = (const float*)d_in[base + 8];
        const float* ffn_b2 = (const float*)d_in[base + 9];

        tgemm<<<dim3(HH / 64, NN / 64), 256>>>(h, gcn_w, nullptr, nullptr, xlin, NN, HH, HH, 0);
        tgemm<<<dim3(3 * HH / 64, NN / 64), 256>>>(h, in_w, in_b, nullptr, qkv, NN, 3 * HH, HH, 0);
        flash_part<<<dim3(NN / 64, 4, SPLITS), 128, flash_smem>>>(qkv, opart, mpart, lpart);
        flash_merge<<<(NN * HH) / 256, 256>>>(opart, mpart, lpart, attn);
        tgemm<<<dim3(HH / 64, NN / 64), 256>>>(attn, out_w, out_b, nullptr, proj, NN, HH, HH, 0);
        cudaMemsetAsync(agg, 0, (size_t)NN * HH * sizeof(float));
        gcn_scatter<<<(EE * 32) / 256, 256>>>(ei, ei + EE, dinv, xlin, agg, EE);
        combine<<<(NN * HH) / 256, 256>>>(agg, xlin, dinv, gcn_b, proj, h, outb, NN * HH);
        tgemm<<<dim3(2 * HH / 64, NN / 64), 256>>>(outb, ffn_w1, ffn_b1, nullptr, ffn, NN, 2 * HH, HH, 1);
        tgemm<<<dim3(HH / 64, NN / 64), 256>>>(ffn, ffn_w2, ffn_b2, outb, h, NN, HH, 2 * HH, 1);
    }

    // head
    tgemm<<<dim3(HH / 64, NN / 64), 256>>>(h, mlp_w1, mlp_b1, nullptr, hid, NN, HH, HH, 1);
    tgemm<<<dim3(NN / 64, NN / 64), 256>>>(hid, mlp_w2, mlp_b2, nullptr, (float*)d_out, NN, NN, HH, 0);
    symmetrize<<<dim3(NN / 64, NN / 64), 256>>>((float*)d_out);
}

// round 8
// speedup vs baseline: 1.2225x; 1.1086x over previous
#include <cuda_runtime.h>
#include <cuda_bf16.h>
#include <stdint.h>
#include <math.h>

#define NN 4096
#define HH 256
#define EE 65536
#define SPLITS 8

// ---------------- device scratch ----------------
__device__ float g_h[NN * HH];
__device__ float g_xlin[NN * HH];
__device__ float g_qkv[NN * 3 * HH];
__device__ float g_attn[NN * HH];
__device__ float g_proj[NN * HH];
__device__ float g_agg[NN * HH];
__device__ float g_out[NN * HH];
__device__ float g_ffn[NN * 2 * HH];
__device__ float g_hid[NN * HH];
__device__ float g_deg[NN];
__device__ float g_dinv[NN];
__device__ float g_opart[SPLITS * NN * HH];
__device__ float g_mpart[SPLITS * 4 * NN];
__device__ float g_lpart[SPLITS * 4 * NN];

// ---------------- helpers ----------------
__device__ __forceinline__ uint32_t f2tf(float f) {
    uint32_t u;
    asm("cvt.rna.tf32.f32 %0, %1;" : "=r"(u) : "f"(f));
    return u;
}

__device__ __forceinline__ void mma_tf32(float c[4], const uint32_t a[4], const uint32_t b[2]) {
    asm volatile(
        "mma.sync.aligned.m16n8k8.row.col.f32.tf32.tf32.f32 "
        "{%0,%1,%2,%3},{%4,%5,%6,%7},{%8,%9},{%0,%1,%2,%3};\n"
        : "+f"(c[0]), "+f"(c[1]), "+f"(c[2]), "+f"(c[3])
        : "r"(a[0]), "r"(a[1]), "r"(a[2]), "r"(a[3]), "r"(b[0]), "r"(b[1]));
}

__device__ __forceinline__ void cpa16(void* s, const void* g) {
    uint32_t sa = (uint32_t)__cvta_generic_to_shared(s);
    asm volatile("cp.async.cg.shared.global [%0], [%1], 16;\n" :: "r"(sa), "l"(g) : "memory");
}
#define CP_COMMIT asm volatile("cp.async.commit_group;\n" ::: "memory")
template<int W> __device__ __forceinline__ void cp_wait() {
    asm volatile("cp.async.wait_group %0;\n" :: "n"(W) : "memory");
}

// ---------------- TF32 GEMM: 64x64 tile, 4 warps, 3-stage cp.async (round-5 config) ----------------
// C[M,Nn] = act(A[M,K] @ W[Nn,K]^T + bias + add)
// conv==1 (qkv mode): store tf32 bit-patterns; cols < 256 (Q) pre-scaled by 0.125.
#define GBK 16

__global__ void __launch_bounds__(128) tgemm(
    const float* __restrict__ A, const float* __restrict__ W,
    const float* __restrict__ bias, const float* __restrict__ add,
    float* __restrict__ C, int M, int Nn, int K, int relu, int conv) {
    __shared__ float As[3][64][20];
    __shared__ float Ws[3][64][20];

    int tid = threadIdx.x;
    int lane = tid & 31, wid = tid >> 5;
    int warp_m = wid & 1, warp_n = wid >> 1;     // 2x2 warps, 32x32 each
    int m0 = blockIdx.y * 64, n0 = blockIdx.x * 64;

    float c[2][4][4];
#pragma unroll
    for (int mt = 0; mt < 2; mt++)
#pragma unroll
        for (int nt = 0; nt < 4; nt++)
#pragma unroll
            for (int r = 0; r < 4; r++) c[mt][nt][r] = 0.f;

    int nIter = K / GBK;

    auto issue = [&](int it, int buf) {
        int k0 = it * GBK;
#pragma unroll
        for (int j = 0; j < 2; j++) {
            int cc = tid + 128 * j;
            int row = cc >> 2, ch = (cc & 3) * 4;
            cpa16(&As[buf][row][ch], &A[(long)(m0 + row) * K + k0 + ch]);
            cpa16(&Ws[buf][row][ch], &W[(long)(n0 + row) * K + k0 + ch]);
        }
    };

    issue(0, 0); CP_COMMIT;
    issue(1, 1); CP_COMMIT;

    for (int i = 0; i < nIter; i++) {
        int buf = i % 3;
        if (i + 2 < nIter) { issue(i + 2, (i + 2) % 3); CP_COMMIT; cp_wait<2>(); }
        else if (i + 1 < nIter) cp_wait<1>();
        else cp_wait<0>();
        __syncthreads();

#pragma unroll
        for (int ks = 0; ks < GBK; ks += 8) {
            uint32_t a[2][4], b[4][2];
            int kk = ks + (lane & 3);
#pragma unroll
            for (int mt = 0; mt < 2; mt++) {
                int row = warp_m * 32 + mt * 16 + (lane >> 2);
                a[mt][0] = f2tf(As[buf][row][kk]);
                a[mt][1] = f2tf(As[buf][row + 8][kk]);
                a[mt][2] = f2tf(As[buf][row][kk + 4]);
                a[mt][3] = f2tf(As[buf][row + 8][kk + 4]);
            }
#pragma unroll
            for (int nt = 0; nt < 4; nt++) {
                int nc = warp_n * 32 + nt * 8 + (lane >> 2);
                b[nt][0] = f2tf(Ws[buf][nc][kk]);
                b[nt][1] = f2tf(Ws[buf][nc][kk + 4]);
            }
#pragma unroll
            for (int mt = 0; mt < 2; mt++)
#pragma unroll
                for (int nt = 0; nt < 4; nt++) mma_tf32(c[mt][nt], a[mt], b[nt]);
        }
        __syncthreads();
    }

    // epilogue
#pragma unroll
    for (int mt = 0; mt < 2; mt++) {
        int rb = m0 + warp_m * 32 + mt * 16 + (lane >> 2);
#pragma unroll
        for (int nt = 0; nt < 4; nt++) {
            int cb = n0 + warp_n * 32 + nt * 8 + 2 * (lane & 3);
#pragma unroll
            for (int r = 0; r < 4; r++) {
                int mm = rb + (r >> 1) * 8;
                int nn = cb + (r & 1);
                float v = c[mt][nt][r];
                if (bias) v += bias[nn];
                if (add)  v += add[(long)mm * Nn + nn];
                if (relu) v = fmaxf(v, 0.f);
                if (conv) {   // qkv mode: pre-converted tf32 bits; Q section pre-scaled
                    if (nn < HH) v *= 0.125f;
                    C[(long)mm * Nn + nn] = __uint_as_float(f2tf(v));
                } else {
                    C[(long)mm * Nn + nn] = v;
                }
            }
        }
    }
}

// ---------------- TF32 flash attention: operands pre-converted to tf32 bits ----------------
// qkv holds tf32 BIT PATTERNS (Q pre-scaled by 0.125). No cvt in the hot loop except P.
#define KST 68
#define VST 72
#define KBUF (64 * KST)
#define VBUF (64 * VST)

__global__ void __launch_bounds__(128) flash_part(const float* __restrict__ qkv,
                                                  float* __restrict__ opart,
                                                  float* __restrict__ mpart,
                                                  float* __restrict__ lpart) {
    extern __shared__ float sm[];
    float* Ks = sm;                 // [2][64][KST]; reused as P after S-matmul
    float* Vs = sm + 2 * KBUF;      // [2][64][VST]

    int tid = threadIdx.x;
    int lane = tid & 31, wid = tid >> 5;
    int q0 = blockIdx.x * 64;
    int head = blockIdx.y;
    int split = blockIdx.z;
    const int C3 = 3 * HH;
    const int qoff = head * 64, koff = HH + head * 64, voff = 2 * HH + head * 64;

    // Q fragments: already tf32 bits, already scaled
    uint32_t qa[8][4];
    {
        int r = q0 + wid * 16 + (lane >> 2);
#pragma unroll
        for (int kt = 0; kt < 8; kt++) {
            int d = kt * 8 + (lane & 3);
            qa[kt][0] = __float_as_uint(qkv[(long)r * C3 + qoff + d]);
            qa[kt][1] = __float_as_uint(qkv[(long)(r + 8) * C3 + qoff + d]);
            qa[kt][2] = __float_as_uint(qkv[(long)r * C3 + qoff + d + 4]);
            qa[kt][3] = __float_as_uint(qkv[(long)(r + 8) * C3 + qoff + d + 4]);
        }
    }

    float m0 = -1e30f, m1 = -1e30f, l0 = 0.f, l1 = 0.f;
    float o[8][4];
#pragma unroll
    for (int nt = 0; nt < 8; nt++)
#pragma unroll
        for (int r = 0; r < 4; r++) o[nt][r] = 0.f;

    int kbase = split * (NN / SPLITS);
    const int nIter = (NN / SPLITS) / 64;

    auto issue = [&](int it, int buf) {
        int k0 = kbase + it * 64;
#pragma unroll
        for (int j = 0; j < 8; j++) {
            int cc = tid + 128 * j;
            int key = cc >> 4, ch = (cc & 15) * 4;
            cpa16(&Ks[buf * KBUF + key * KST + ch], &qkv[(long)(k0 + key) * C3 + koff + ch]);
            cpa16(&Vs[buf * VBUF + key * VST + ch], &qkv[(long)(k0 + key) * C3 + voff + ch]);
        }
    };

    issue(0, 0); CP_COMMIT;
    int cur = 0;
    for (int i = 0; i < nIter; i++) {
        if (i + 1 < nIter) { issue(i + 1, cur ^ 1); CP_COMMIT; cp_wait<1>(); }
        else cp_wait<0>();
        __syncthreads();

        float* Kc = Ks + cur * KBUF;
        const float* Vc = Vs + cur * VBUF;

        // S = Q K^T  (K already tf32 bits)
        float s[8][4];
#pragma unroll
        for (int nt = 0; nt < 8; nt++)
#pragma unroll
            for (int r = 0; r < 4; r++) s[nt][r] = 0.f;
#pragma unroll
        for (int kt = 0; kt < 8; kt++) {
            int kk = kt * 8 + (lane & 3);
            uint32_t b[2];
#pragma unroll
            for (int nt = 0; nt < 8; nt++) {
                int key = nt * 8 + (lane >> 2);
                b[0] = __float_as_uint(Kc[key * KST + kk]);
                b[1] = __float_as_uint(Kc[key * KST + kk + 4]);
                mma_tf32(s[nt], qa[kt], b);
            }
        }

        // online softmax
        float mx0 = -1e30f, mx1 = -1e30f;
#pragma unroll
        for (int nt = 0; nt < 8; nt++) {
            mx0 = fmaxf(mx0, fmaxf(s[nt][0], s[nt][1]));
            mx1 = fmaxf(mx1, fmaxf(s[nt][2], s[nt][3]));
        }
#pragma unroll
        for (int off = 1; off <= 2; off <<= 1) {
            mx0 = fmaxf(mx0, __shfl_xor_sync(0xffffffffu, mx0, off));
            mx1 = fmaxf(mx1, __shfl_xor_sync(0xffffffffu, mx1, off));
        }
        float mn0 = fmaxf(m0, mx0), mn1 = fmaxf(m1, mx1);
        float sum0 = 0.f, sum1 = 0.f;
#pragma unroll
        for (int nt = 0; nt < 8; nt++) {
            s[nt][0] = __expf(s[nt][0] - mn0);
            s[nt][1] = __expf(s[nt][1] - mn0);
            s[nt][2] = __expf(s[nt][2] - mn1);
            s[nt][3] = __expf(s[nt][3] - mn1);
            sum0 += s[nt][0] + s[nt][1];
            sum1 += s[nt][2] + s[nt][3];
        }
#pragma unroll
        for (int off = 1; off <= 2; off <<= 1) {
            sum0 += __shfl_xor_sync(0xffffffffu, sum0, off);
            sum1 += __shfl_xor_sync(0xffffffffu, sum1, off);
        }
        float e0 = __expf(m0 - mn0), e1 = __expf(m1 - mn1);
        l0 = l0 * e0 + sum0;
        l1 = l1 * e1 + sum1;
        m0 = mn0; m1 = mn1;
#pragma unroll
        for (int nt = 0; nt < 8; nt++) {
            o[nt][0] *= e0; o[nt][1] *= e0;
            o[nt][2] *= e1; o[nt][3] *= e1;
        }

        __syncthreads();   // Kc readers done -> reuse as P

        // P (tf32 bits) into Kc region
        {
            int r = wid * 16 + (lane >> 2);
#pragma unroll
            for (int nt = 0; nt < 8; nt++) {
                int cb = nt * 8 + 2 * (lane & 3);
                Kc[r * KST + cb]           = __uint_as_float(f2tf(s[nt][0]));
                Kc[r * KST + cb + 1]       = __uint_as_float(f2tf(s[nt][1]));
                Kc[(r + 8) * KST + cb]     = __uint_as_float(f2tf(s[nt][2]));
                Kc[(r + 8) * KST + cb + 1] = __uint_as_float(f2tf(s[nt][3]));
            }
        }
        __syncwarp();

        // O += P V  (V already tf32 bits)
#pragma unroll
        for (int kt = 0; kt < 8; kt++) {
            int r = wid * 16 + (lane >> 2);
            int kk = kt * 8 + (lane & 3);
            uint32_t a[4];
            a[0] = __float_as_uint(Kc[r * KST + kk]);
            a[1] = __float_as_uint(Kc[(r + 8) * KST + kk]);
            a[2] = __float_as_uint(Kc[r * KST + kk + 4]);
            a[3] = __float_as_uint(Kc[(r + 8) * KST + kk + 4]);
            uint32_t b[2];
#pragma unroll
            for (int nt = 0; nt < 8; nt++) {
                int dd = nt * 8 + (lane >> 2);
                b[0] = __float_as_uint(Vc[kk * VST + dd]);
                b[1] = __float_as_uint(Vc[(kk + 4) * VST + dd]);
                mma_tf32(o[nt], a, b);
            }
        }
        __syncthreads();
        cur ^= 1;
    }

    int r = q0 + wid * 16 + (lane >> 2);
    float* ob = opart + (long)split * NN * HH;
#pragma unroll
    for (int nt = 0; nt < 8; nt++) {
        int cb = head * 64 + nt * 8 + 2 * (lane & 3);
        ob[(long)r * HH + cb]           = o[nt][0];
        ob[(long)r * HH + cb + 1]       = o[nt][1];
        ob[(long)(r + 8) * HH + cb]     = o[nt][2];
        ob[(long)(r + 8) * HH + cb + 1] = o[nt][3];
    }
    if ((lane & 3) == 0) {
        int base = (split * 4 + head) * NN;
        mpart[base + r] = m0;     lpart[base + r] = l0;
        mpart[base + r + 8] = m1; lpart[base + r + 8] = l1;
    }
}

__global__ void flash_merge(const float* __restrict__ opart, const float* __restrict__ mpart,
                            const float* __restrict__ lpart, float* __restrict__ out) {
    int idx = blockIdx.x * blockDim.x + threadIdx.x;
    if (idx >= NN * HH) return;
    int row = idx >> 8, c = idx & 255, head = c >> 6;
    float mv[SPLITS], lv[SPLITS];
    float mmax = -1e30f;
#pragma unroll
    for (int s = 0; s < SPLITS; s++) {
        mv[s] = mpart[(s * 4 + head) * NN + row];
        lv[s] = lpart[(s * 4 + head) * NN + row];
        mmax = fmaxf(mmax, mv[s]);
    }
    float num = 0.f, den = 0.f;
#pragma unroll
    for (int s = 0; s < SPLITS; s++) {
        float w = __expf(mv[s] - mmax);
        num += opart[(long)s * NN * HH + idx] * w;
        den += lv[s] * w;
    }
    out[idx] = num / den;
}

// ---------------- GCN helpers ----------------
__global__ void deg_init(float* deg, int n) {
    int i = blockIdx.x * blockDim.x + threadIdx.x;
    if (i < n) deg[i] = 1.f;
}
__global__ void deg_count(const int* __restrict__ dst, float* deg, int e) {
    int i = blockIdx.x * blockDim.x + threadIdx.x;
    if (i < e) atomicAdd(&deg[dst[i]], 1.f);
}
__global__ void dinv_kernel(const float* __restrict__ deg, float* dinv, int n) {
    int i = blockIdx.x * blockDim.x + threadIdx.x;
    if (i < n) dinv[i] = rsqrtf(deg[i]);
}

__global__ void gcn_scatter(const int* __restrict__ src, const int* __restrict__ dst,
                            const float* __restrict__ dinv, const float* __restrict__ xlin,
                            float* __restrict__ agg, int e) {
    int w = (blockIdx.x * blockDim.x + threadIdx.x) >> 5;
    int lane = threadIdx.x & 31;
    if (w >= e) return;
    int s = src[w], d = dst[w];
    float coef = dinv[s] * dinv[d];
    const float* xs = xlin + (long)s * HH;
    float* ad = agg + (long)d * HH;
#pragma unroll
    for (int k = 0; k < HH / 32; k++)
        atomicAdd(&ad[lane + 32 * k], xs[lane + 32 * k] * coef);
}

__global__ void combine(const float* __restrict__ agg, const float* __restrict__ xlin,
                        const float* __restrict__ dinv, const float* __restrict__ gcn_b,
                        const float* __restrict__ proj, const float* __restrict__ h,
                        float* __restrict__ out, int total) {
    int idx = blockIdx.x * blockDim.x + threadIdx.x;
    if (idx >= total) return;
    int i = idx >> 8, c = idx & 255;
    float dv = dinv[i];
    out[idx] = agg[idx] + xlin[idx] * dv * dv + gcn_b[c] + proj[idx] + 2.f * h[idx];
}

// ---------------- tiled symmetrize ----------------
__global__ void __launch_bounds__(256) symmetrize(float* __restrict__ o) {
    int ti = blockIdx.y, tj = blockIdx.x;
    if (tj < ti) return;
    __shared__ float As[64][65];
    __shared__ float Bs[64][65];
    int tid = threadIdx.x;
    int r = tid >> 2, c0 = (tid & 3) * 16;
    long base_a = (long)ti * 64 * NN + tj * 64;
    long base_b = (long)tj * 64 * NN + ti * 64;

#pragma unroll
    for (int j = 0; j < 16; j += 4) {
        float4 va = *(const float4*)&o[base_a + (long)r * NN + c0 + j];
        float4 vb = *(const float4*)&o[base_b + (long)r * NN + c0 + j];
        As[r][c0 + j] = va.x; As[r][c0 + j + 1] = va.y;
        As[r][c0 + j + 2] = va.z; As[r][c0 + j + 3] = va.w;
        Bs[r][c0 + j] = vb.x; Bs[r][c0 + j + 1] = vb.y;
        Bs[r][c0 + j + 2] = vb.z; Bs[r][c0 + j + 3] = vb.w;
    }
    __syncthreads();

#pragma unroll
    for (int j = 0; j < 16; j += 4) {
        float4 wa, wb;
        wa.x = 0.5f * (As[r][c0 + j]     + Bs[c0 + j][r]);
        wa.y = 0.5f * (As[r][c0 + j + 1] + Bs[c0 + j + 1][r]);
        wa.z = 0.5f * (As[r][c0 + j + 2] + Bs[c0 + j + 2][r]);
        wa.w = 0.5f * (As[r][c0 + j + 3] + Bs[c0 + j + 3][r]);
        *(float4*)&o[base_a + (long)r * NN + c0 + j] = wa;
        if (ti != tj) {
            wb.x = 0.5f * (Bs[r][c0 + j]     + As[c0 + j][r]);
            wb.y = 0.5f * (Bs[r][c0 + j + 1] + As[c0 + j + 1][r]);
            wb.z = 0.5f * (Bs[r][c0 + j + 2] + As[c0 + j + 2][r]);
            wb.w = 0.5f * (Bs[r][c0 + j + 3] + As[c0 + j + 3][r]);
            *(float4*)&o[base_b + (long)r * NN + c0 + j] = wb;
        }
    }
}

// ---------------- launch ----------------
extern "C" void kernel_launch(void* const* d_in, const int* in_sizes, int n_in,
                              void* d_out, int out_size) {
    const float* x      = (const float*)d_in[0];
    const int*   ei     = (const int*)d_in[1];
    const float* pre_w  = (const float*)d_in[2];
    const float* pre_b  = (const float*)d_in[3];
    const float* mlp_w1 = (const float*)d_in[24];
    const float* mlp_b1 = (const float*)d_in[25];
    const float* mlp_w2 = (const float*)d_in[26];
    const float* mlp_b2 = (const float*)d_in[27];

    float *h, *xlin, *qkv, *attn, *proj, *agg, *outb, *ffn, *hid, *deg, *dinv;
    float *opart, *mpart, *lpart;
    cudaGetSymbolAddress((void**)&h,    g_h);
    cudaGetSymbolAddress((void**)&xlin, g_xlin);
    cudaGetSymbolAddress((void**)&qkv,  g_qkv);
    cudaGetSymbolAddress((void**)&attn, g_attn);
    cudaGetSymbolAddress((void**)&proj, g_proj);
    cudaGetSymbolAddress((void**)&agg,  g_agg);
    cudaGetSymbolAddress((void**)&outb, g_out);
    cudaGetSymbolAddress((void**)&ffn,  g_ffn);
    cudaGetSymbolAddress((void**)&hid,  g_hid);
    cudaGetSymbolAddress((void**)&deg,  g_deg);
    cudaGetSymbolAddress((void**)&dinv, g_dinv);
    cudaGetSymbolAddress((void**)&opart, g_opart);
    cudaGetSymbolAddress((void**)&mpart, g_mpart);
    cudaGetSymbolAddress((void**)&lpart, g_lpart);

    const int flash_smem = (2 * KBUF + 2 * VBUF) * (int)sizeof(float);  // 71680
    cudaFuncSetAttribute(flash_part, cudaFuncAttributeMaxDynamicSharedMemorySize, flash_smem);

    deg_init<<<(NN + 255) / 256, 256>>>(deg, NN);
    deg_count<<<(EE + 255) / 256, 256>>>(ei + EE, deg, EE);
    dinv_kernel<<<(NN + 255) / 256, 256>>>(deg, dinv, NN);

    // pre: h = relu(x @ pre_w^T + pre_b)
    tgemm<<<dim3(HH / 64, NN / 64), 128>>>(x, pre_w, pre_b, nullptr, h, NN, HH, 128, 1, 0);

    for (int L = 0; L < 2; L++) {
        int base = 4 + L * 10;
        const float* gcn_w  = (const float*)d_in[base + 0];
        const float* gcn_b  = (const float*)d_in[base + 1];
        const float* in_w   = (const float*)d_in[base + 2];
        const float* in_b   = (const float*)d_in[base + 3];
        const float* out_w  = (const float*)d_in[base + 4];
        const float* out_b  = (const float*)d_in[base + 5];
        const float* ffn_w1 = (const float*)d_in[base + 6];
        const float* ffn_b1 = (const float*)d_in[base + 7];
        const float* ffn_w2 = (const float*)d_in[base + 8];
        const float* ffn_b2 = (const float*)d_in[base + 9];

        tgemm<<<dim3(HH / 64, NN / 64), 128>>>(h, gcn_w, nullptr, nullptr, xlin, NN, HH, HH, 0, 0);
        // qkv in tf32-bit form (Q pre-scaled by 1/8)
        tgemm<<<dim3(3 * HH / 64, NN / 64), 128>>>(h, in_w, in_b, nullptr, qkv, NN, 3 * HH, HH, 0, 1);
        flash_part<<<dim3(NN / 64, 4, SPLITS), 128, flash_smem>>>(qkv, opart, mpart, lpart);
        flash_merge<<<(NN * HH) / 256, 256>>>(opart, mpart, lpart, attn);
        tgemm<<<dim3(HH / 64, NN / 64), 128>>>(attn, out_w, out_b, nullptr, proj, NN, HH, HH, 0, 0);
        cudaMemsetAsync(agg, 0, (size_t)NN * HH * sizeof(float));
        gcn_scatter<<<(EE * 32) / 256, 256>>>(ei, ei + EE, dinv, xlin, agg, EE);
        combine<<<(NN * HH) / 256, 256>>>(agg, xlin, dinv, gcn_b, proj, h, outb, NN * HH);
        tgemm<<<dim3(2 * HH / 64, NN / 64), 128>>>(outb, ffn_w1, ffn_b1, nullptr, ffn, NN, 2 * HH, HH, 1, 0);
        tgemm<<<dim3(HH / 64, NN / 64), 128>>>(ffn, ffn_w2, ffn_b2, outb, h, NN, HH, 2 * HH, 1, 0);
    }

    // head
    tgemm<<<dim3(HH / 64, NN / 64), 128>>>(h, mlp_w1, mlp_b1, nullptr, hid, NN, HH, HH, 1, 0);
    tgemm<<<dim3(NN / 64, NN / 64), 128>>>(hid, mlp_w2, mlp_b2, nullptr, (float*)d_out, NN, NN, HH, 0, 0);
    symmetrize<<<dim3(NN / 64, NN / 64), 256>>>((float*)d_out);
}